// round 1
// baseline (speedup 1.0000x reference)
#include <cuda_runtime.h>
#include <math.h>

// Problem constants
#define B_ 64
#define T_ 200
#define E_ 512
#define H_ 8
#define D_ 64
#define M_ (B_ * T_)            // 12800 rows
#define SCALE_ 0.04419417382415922f  // 512^-0.5
#define LN_EPS 1e-5f

// ---------------- scratch (device globals; no allocation allowed) ----------------
__device__ float g_h[M_ * E_];          // LN output (reused 3x)
__device__ float g_qkv[M_ * 3 * E_];    // self qkv / cross qv
__device__ float g_kca[M_ * E_];        // cross k
__device__ float g_ao[M_ * E_];         // attention output (reused 2x)
__device__ float g_idx2[M_ * E_];
__device__ float g_idx3[M_ * E_];
__device__ float g_mid[M_ * 4 * E_];    // FFN hidden
__device__ float g_Wsa[E_ * 3 * E_];    // packed self qkv weights [E, 3E]
__device__ float g_Wqvca[E_ * 2 * E_];  // packed cross q,v weights [E, 2E]
__device__ float g_Wkca[E_ * E_];       // packed cross k weights [E, E]

// ---------------- weight repack: [H,E,D] (x nmats) -> [E, nmats*E] ----------------
__global__ void pack_weights(const float* __restrict__ w0,
                             const float* __restrict__ w1,
                             const float* __restrict__ w2,
                             float* __restrict__ out, int nmats) {
    int i = blockIdx.x * blockDim.x + threadIdx.x;
    int total = E_ * nmats * E_;
    if (i >= total) return;
    int cols = nmats * E_;
    int e = i / cols;
    int c = i % cols;
    int m = c / E_;
    int hd = c % E_;
    const float* w = (m == 0) ? w0 : ((m == 1) ? w1 : w2);
    int h = hd >> 6, d = hd & 63;
    out[i] = w[((size_t)h * E_ + e) * D_ + d];
}

// ---------------- layernorm: one block per row, 128 threads x float4 ----------------
__global__ void ln_kernel(const float* __restrict__ x, const float* __restrict__ g,
                          const float* __restrict__ b, float* __restrict__ y) {
    int row = blockIdx.x;
    const float4* xr = (const float4*)(x + (size_t)row * E_);
    float4 v = xr[threadIdx.x];
    float s  = v.x + v.y + v.z + v.w;
    float ss = v.x * v.x + v.y * v.y + v.z * v.z + v.w * v.w;
    #pragma unroll
    for (int o = 16; o > 0; o >>= 1) {
        s  += __shfl_xor_sync(~0u, s, o);
        ss += __shfl_xor_sync(~0u, ss, o);
    }
    __shared__ float sh[8];
    int w = threadIdx.x >> 5, l = threadIdx.x & 31;
    if (l == 0) { sh[w] = s; sh[4 + w] = ss; }
    __syncthreads();
    s  = sh[0] + sh[1] + sh[2] + sh[3];
    ss = sh[4] + sh[5] + sh[6] + sh[7];
    float mu   = s * (1.0f / E_);
    float var  = ss * (1.0f / E_) - mu * mu;
    float rstd = rsqrtf(var + LN_EPS);
    float4 gv = ((const float4*)g)[threadIdx.x];
    float4 bv = ((const float4*)b)[threadIdx.x];
    float4 o;
    o.x = (v.x - mu) * rstd * gv.x + bv.x;
    o.y = (v.y - mu) * rstd * gv.y + bv.y;
    o.z = (v.z - mu) * rstd * gv.z + bv.z;
    o.w = (v.w - mu) * rstd * gv.w + bv.w;
    ((float4*)(y + (size_t)row * E_))[threadIdx.x] = o;
}

// ---------------- SGEMM 128x128x8, 256 threads, 8x8 microtile ----------------
// C[M,N] = A[M,K] @ B[K,N], row-major. Epilogue: +bias, relu, row-mask zero, +residual.
// Requires M%128==0, N%128==0, K%8==0 (always true here).
__global__ __launch_bounds__(256, 1) void sgemm_kernel(
    const float* __restrict__ A, const float* __restrict__ B,
    float* __restrict__ C, int N, int K,
    const float* __restrict__ bias, const float* __restrict__ residual,
    const int* __restrict__ rowmask, int maskColEnd, int doRelu)
{
    __shared__ float As[8][128];
    __shared__ float Bs[8][128];
    int tid = threadIdx.x;
    int bm = blockIdx.y * 128;
    int bn = blockIdx.x * 128;
    int arow = tid >> 1, acol = (tid & 1) * 4;
    int brow = tid >> 5, bcol = (tid & 31) * 4;
    int tm = (tid >> 4) * 8, tn = (tid & 15) * 8;
    float acc[8][8] = {};
    const float* Aptr = A + (size_t)(bm + arow) * K + acol;
    const float* Bptr = B + (size_t)brow * N + bn + bcol;
    for (int k0 = 0; k0 < K; k0 += 8) {
        float4 av = *(const float4*)(Aptr + k0);
        float4 bv = *(const float4*)(Bptr + (size_t)k0 * N);
        As[acol + 0][arow] = av.x;
        As[acol + 1][arow] = av.y;
        As[acol + 2][arow] = av.z;
        As[acol + 3][arow] = av.w;
        *(float4*)&Bs[brow][bcol] = bv;
        __syncthreads();
        #pragma unroll
        for (int k = 0; k < 8; k++) {
            float af[8], bf[8];
            *(float4*)(af)     = *(const float4*)&As[k][tm];
            *(float4*)(af + 4) = *(const float4*)&As[k][tm + 4];
            *(float4*)(bf)     = *(const float4*)&Bs[k][tn];
            *(float4*)(bf + 4) = *(const float4*)&Bs[k][tn + 4];
            #pragma unroll
            for (int i = 0; i < 8; i++)
                #pragma unroll
                for (int j = 0; j < 8; j++)
                    acc[i][j] += af[i] * bf[j];
        }
        __syncthreads();
    }
    #pragma unroll
    for (int i = 0; i < 8; i++) {
        int row = bm + tm + i;
        int mz = rowmask ? (rowmask[row] == 0) : 0;
        float* crow = C + (size_t)row * N + bn + tn;
        const float* rrow = residual ? (residual + (size_t)row * N + bn + tn) : nullptr;
        #pragma unroll
        for (int j = 0; j < 8; j++) {
            float c = acc[i][j];
            int n = bn + tn + j;
            if (bias) c += bias[n];
            if (doRelu) c = fmaxf(c, 0.0f);
            if (mz && n < maskColEnd) c = 0.0f;
            if (rrow) c += rrow[j];
            crow[j] = c;
        }
    }
}

// ---------------- attention: one block per (b,h), causal softmax ----------------
// Q/K/V read from strided buffers (row stride in floats), O written to [B*T, E] at head offset.
#define KPAD 67
#define ATTN_SMEM ((3 * T_ * KPAD + 8 * T_) * 4)

__global__ __launch_bounds__(256, 1) void attn_kernel(
    const float* __restrict__ Q, int qs,
    const float* __restrict__ Kp, int ks,
    const float* __restrict__ V, int vs,
    float* __restrict__ O)
{
    extern __shared__ float sm[];
    float* sK = sm;
    float* sV = sK + T_ * KPAD;
    float* sQ = sV + T_ * KPAD;
    float* sP = sQ + T_ * KPAD;   // 8 warps x T_ probs
    int bh = blockIdx.x;
    int b = bh / H_, h = bh % H_;
    size_t base = (size_t)b * T_;
    const float* qb = Q  + base * qs + h * D_;
    const float* kb = Kp + base * ks + h * D_;
    const float* vb = V  + base * vs + h * D_;
    float* ob = O + base * E_ + h * D_;

    for (int i = threadIdx.x; i < T_ * D_; i += blockDim.x) {
        int t = i >> 6, d = i & 63;
        sK[t * KPAD + d] = kb[(size_t)t * ks + d];
        sV[t * KPAD + d] = vb[(size_t)t * vs + d];
        sQ[t * KPAD + d] = qb[(size_t)t * qs + d];
    }
    __syncthreads();

    int w = threadIdx.x >> 5, l = threadIdx.x & 31;
    float* p = sP + w * T_;
    for (int t = w; t < T_; t += 8) {
        const float* qr = sQ + t * KPAD;
        float mx = -1e30f;
        for (int s = l; s <= t; s += 32) {
            const float* kr = sK + s * KPAD;
            float dot = 0.0f;
            #pragma unroll
            for (int d = 0; d < 64; d++) dot += qr[d] * kr[d];
            dot *= SCALE_;
            p[s] = dot;
            mx = fmaxf(mx, dot);
        }
        #pragma unroll
        for (int o = 16; o > 0; o >>= 1) mx = fmaxf(mx, __shfl_xor_sync(~0u, mx, o));
        float sum = 0.0f;
        for (int s = l; s <= t; s += 32) {
            float e = __expf(p[s] - mx);
            p[s] = e;
            sum += e;
        }
        #pragma unroll
        for (int o = 16; o > 0; o >>= 1) sum += __shfl_xor_sync(~0u, sum, o);
        float inv = 1.0f / sum;
        __syncwarp();                 // p[] fully written before cross-lane reads
        float a0 = 0.0f, a1 = 0.0f;
        for (int s = 0; s <= t; s++) {
            float pv = p[s];
            a0 += pv * sV[s * KPAD + l];
            a1 += pv * sV[s * KPAD + l + 32];
        }
        ob[(size_t)t * E_ + l]      = a0 * inv;
        ob[(size_t)t * E_ + l + 32] = a1 * inv;
        __syncwarp();                 // all lanes done reading p[] before next row overwrites
    }
}

// ---------------- orchestration ----------------
extern "C" void kernel_launch(void* const* d_in, const int* in_sizes, int n_in,
                              void* d_out, int out_size) {
    const float* idx      = (const float*)d_in[0];
    const float* memory   = (const float*)d_in[1];
    const int*   src_mask = (const int*)d_in[2];
    const int*   pred_mask= (const int*)d_in[3];
    const float* sa_wq = (const float*)d_in[4];
    const float* sa_wk = (const float*)d_in[5];
    const float* sa_wv = (const float*)d_in[6];
    const float* sa_wo = (const float*)d_in[7];
    const float* sa_bo = (const float*)d_in[8];
    const float* ca_wq = (const float*)d_in[9];
    const float* ca_wk = (const float*)d_in[10];
    const float* ca_wv = (const float*)d_in[11];
    const float* ca_wo = (const float*)d_in[12];
    const float* ca_bo = (const float*)d_in[13];
    const float* f_w1  = (const float*)d_in[14];
    const float* f_b1  = (const float*)d_in[15];
    const float* f_w2  = (const float*)d_in[16];
    const float* f_b2  = (const float*)d_in[17];
    const float* ln1_g = (const float*)d_in[18];
    const float* ln1_b = (const float*)d_in[19];
    const float* ln2_g = (const float*)d_in[20];
    const float* ln2_b = (const float*)d_in[21];
    const float* ln3_g = (const float*)d_in[22];
    const float* ln3_b = (const float*)d_in[23];
    float* out = (float*)d_out;

    float *h, *qkv, *kca, *ao, *idx2, *idx3, *mid, *Wsa, *Wqvca, *Wkca;
    cudaGetSymbolAddress((void**)&h,    g_h);
    cudaGetSymbolAddress((void**)&qkv,  g_qkv);
    cudaGetSymbolAddress((void**)&kca,  g_kca);
    cudaGetSymbolAddress((void**)&ao,   g_ao);
    cudaGetSymbolAddress((void**)&idx2, g_idx2);
    cudaGetSymbolAddress((void**)&idx3, g_idx3);
    cudaGetSymbolAddress((void**)&mid,  g_mid);
    cudaGetSymbolAddress((void**)&Wsa,  g_Wsa);
    cudaGetSymbolAddress((void**)&Wqvca,g_Wqvca);
    cudaGetSymbolAddress((void**)&Wkca, g_Wkca);

    cudaFuncSetAttribute(attn_kernel, cudaFuncAttributeMaxDynamicSharedMemorySize, ATTN_SMEM);

    // weight repacks
    pack_weights<<<(E_ * 3 * E_ + 255) / 256, 256>>>(sa_wq, sa_wk, sa_wv, Wsa, 3);
    pack_weights<<<(E_ * 2 * E_ + 255) / 256, 256>>>(ca_wq, ca_wv, ca_wv, Wqvca, 2);
    pack_weights<<<(E_ * E_ + 255) / 256, 256>>>(ca_wk, ca_wk, ca_wk, Wkca, 1);

    dim3 gN512 (512  / 128, M_ / 128);
    dim3 gN1024(1024 / 128, M_ / 128);
    dim3 gN1536(1536 / 128, M_ / 128);
    dim3 gN2048(2048 / 128, M_ / 128);

    // ---- self-attention block ----
    ln_kernel<<<M_, 128>>>(idx, ln1_g, ln1_b, h);
    // qkv = h @ Wsa ; q,k cols [0,1024) zeroed where pred_mask==0
    sgemm_kernel<<<gN1536, 256>>>(h, Wsa, qkv, 1536, 512,
                                  nullptr, nullptr, pred_mask, 1024, 0);
    attn_kernel<<<B_ * H_, 256, ATTN_SMEM>>>(qkv, 1536, qkv + 512, 1536, qkv + 1024, 1536, ao);
    // idx2 = ao @ sa_wo + sa_bo + idx
    sgemm_kernel<<<gN512, 256>>>(ao, sa_wo, idx2, 512, 512,
                                 sa_bo, idx, nullptr, 0, 0);

    // ---- cross-attention block ----
    ln_kernel<<<M_, 128>>>(idx2, ln2_g, ln2_b, h);
    // qv = h @ [ca_wq | ca_wv]
    sgemm_kernel<<<gN1024, 256>>>(h, Wqvca, qkv, 1024, 512,
                                  nullptr, nullptr, nullptr, 0, 0);
    // kca = memory @ ca_wk, zeroed where src_mask==0
    sgemm_kernel<<<gN512, 256>>>(memory, Wkca, kca, 512, 512,
                                 nullptr, nullptr, src_mask, 512, 0);
    attn_kernel<<<B_ * H_, 256, ATTN_SMEM>>>(qkv, 1024, kca, 512, qkv + 512, 1024, ao);
    // idx3 = ao @ ca_wo + ca_bo + idx2
    sgemm_kernel<<<gN512, 256>>>(ao, ca_wo, idx3, 512, 512,
                                 ca_bo, idx2, nullptr, 0, 0);

    // ---- feed-forward block ----
    ln_kernel<<<M_, 128>>>(idx3, ln3_g, ln3_b, h);
    // mid = relu(h @ f_w1 + f_b1)
    sgemm_kernel<<<gN2048, 256>>>(h, f_w1, mid, 2048, 512,
                                  f_b1, nullptr, nullptr, 0, 1);
    // out = mid @ f_w2 + f_b2 + idx3
    sgemm_kernel<<<gN512, 256>>>(mid, f_w2, out, 512, 2048,
                                 f_b2, idx3, nullptr, 0, 0);
}

// round 4
// speedup vs baseline: 2.9954x; 2.9954x over previous
#include <cuda_runtime.h>
#include <math.h>
#include <cstdint>

// Problem constants
#define B_ 64
#define T_ 200
#define E_ 512
#define H_ 8
#define D_ 64
#define M_ (B_ * T_)            // 12800 rows
#define SCALE_ 0.04419417382415922f  // 512^-0.5
#define LN_EPS 1e-5f

// ---------------- scratch (device globals; no allocation allowed) ----------------
__device__ float g_h[M_ * E_];
__device__ float g_qkv[M_ * 3 * E_];
__device__ float g_kca[M_ * E_];
__device__ float g_ao[M_ * E_];
__device__ float g_idx2[M_ * E_];
__device__ float g_idx3[M_ * E_];
__device__ float g_mid[M_ * 4 * E_];
__device__ float g_WsaT[3 * E_ * E_];   // [1536, 512] row n = out col (K-major)
__device__ float g_WqvT[2 * E_ * E_];   // [1024, 512]
__device__ float g_WkT[E_ * E_];        // [512, 512]
__device__ float g_WoSaT[E_ * E_];
__device__ float g_WoCaT[E_ * E_];
__device__ float g_W1T[4 * E_ * E_];    // [2048, 512]
__device__ float g_W2T[E_ * 4 * E_];    // [512, 2048]

// ======================= helpers =======================
__device__ __forceinline__ uint32_t s2u(const void* p) {
    uint32_t a;
    asm("{ .reg .u64 t; cvta.to.shared.u64 t, %1; cvt.u32.u64 %0, t; }" : "=r"(a) : "l"(p));
    return a;
}
#define SWZ(o) ((o) ^ (((o) >> 3) & 0x70))

__device__ __forceinline__ void cpa16(uint32_t dst, const void* src) {
    asm volatile("cp.async.cg.shared.global [%0], [%1], 16;" :: "r"(dst), "l"(src));
}
__device__ __forceinline__ void ldsm4(uint32_t& r0, uint32_t& r1, uint32_t& r2,
                                      uint32_t& r3, uint32_t addr) {
    asm volatile("ldmatrix.sync.aligned.m8n8.x4.shared.b16 {%0,%1,%2,%3}, [%4];"
                 : "=r"(r0), "=r"(r1), "=r"(r2), "=r"(r3) : "r"(addr));
}
__device__ __forceinline__ void cvt_tf32(uint32_t& r) {
    asm("cvt.rna.tf32.f32 %0, %0;" : "+r"(r));
}
__device__ __forceinline__ void mma_tf32(float* c, const uint32_t* a, const uint32_t* b) {
    asm volatile(
        "mma.sync.aligned.m16n8k8.row.col.f32.tf32.tf32.f32 "
        "{%0,%1,%2,%3}, {%4,%5,%6,%7}, {%8,%9}, {%0,%1,%2,%3};"
        : "+f"(c[0]), "+f"(c[1]), "+f"(c[2]), "+f"(c[3])
        : "r"(a[0]), "r"(a[1]), "r"(a[2]), "r"(a[3]), "r"(b[0]), "r"(b[1]));
}

// ---------------- weight packs ----------------
__global__ void pack_qkv_t(const float* __restrict__ w0, const float* __restrict__ w1,
                           const float* __restrict__ w2, float* __restrict__ out, int nmats) {
    int i = blockIdx.x * blockDim.x + threadIdx.x;
    int total = nmats * E_ * E_;
    if (i >= total) return;
    int e = i & 511;
    int c = i >> 9;
    int m = c >> 9;
    int hd = c & 511;
    const float* w = (m == 0) ? w0 : ((m == 1) ? w1 : w2);
    out[i] = w[((size_t)((hd >> 6) * E_ + e)) * D_ + (hd & 63)];
}

__global__ void transpose_k(const float* __restrict__ in, float* __restrict__ out,
                            int R, int C) {
    __shared__ float t[32][33];
    int c0 = blockIdx.x * 32, r0 = blockIdx.y * 32;
    t[threadIdx.y][threadIdx.x] = in[(size_t)(r0 + threadIdx.y) * C + c0 + threadIdx.x];
    __syncthreads();
    out[(size_t)(c0 + threadIdx.y) * R + r0 + threadIdx.x] = t[threadIdx.x][threadIdx.y];
}

// ---------------- layernorm ----------------
__global__ void ln_kernel(const float* __restrict__ x, const float* __restrict__ g,
                          const float* __restrict__ b, float* __restrict__ y) {
    int row = blockIdx.x;
    const float4* xr = (const float4*)(x + (size_t)row * E_);
    float4 v = xr[threadIdx.x];
    float s  = v.x + v.y + v.z + v.w;
    float ss = v.x * v.x + v.y * v.y + v.z * v.z + v.w * v.w;
    #pragma unroll
    for (int o = 16; o > 0; o >>= 1) {
        s  += __shfl_xor_sync(~0u, s, o);
        ss += __shfl_xor_sync(~0u, ss, o);
    }
    __shared__ float sh[8];
    int w = threadIdx.x >> 5, l = threadIdx.x & 31;
    if (l == 0) { sh[w] = s; sh[4 + w] = ss; }
    __syncthreads();
    s  = sh[0] + sh[1] + sh[2] + sh[3];
    ss = sh[4] + sh[5] + sh[6] + sh[7];
    float mu   = s * (1.0f / E_);
    float var  = ss * (1.0f / E_) - mu * mu;
    float rstd = rsqrtf(var + LN_EPS);
    float4 gv = ((const float4*)g)[threadIdx.x];
    float4 bv = ((const float4*)b)[threadIdx.x];
    float4 o;
    o.x = (v.x - mu) * rstd * gv.x + bv.x;
    o.y = (v.y - mu) * rstd * gv.y + bv.y;
    o.z = (v.z - mu) * rstd * gv.z + bv.z;
    o.w = (v.w - mu) * rstd * gv.w + bv.w;
    ((float4*)(y + (size_t)row * E_))[threadIdx.x] = o;
}

// ======================= tf32 mma.sync GEMM =======================
// C[M,N] = A[M,K] @ Bt[N,K]^T. Block 128x128, K staged 32 floats, double buffer.
// 8 warps: warp grid 2(M) x 4(N), warp tile 64x32.
#define TCG_SMEM (4 * 16384)   // A0,B0,A1,B1 each 128x32 floats = 16KB

__global__ __launch_bounds__(256, 2) void tc_gemm(
    const float* __restrict__ A, const float* __restrict__ Bt, float* __restrict__ C,
    int N, int K, const float* __restrict__ bias, const float* __restrict__ residual,
    const int* __restrict__ rowmask, int maskColEnd, int doRelu)
{
    extern __shared__ __align__(1024) char smem[];
    uint32_t sb = s2u(smem);
    uint32_t sA0 = sb, sB0 = sb + 16384, sA1 = sb + 32768, sB1 = sb + 49152;

    int tid = threadIdx.x;
    int bn = blockIdx.x * 128, bm = blockIdx.y * 128;
    int wid = tid >> 5, lane = tid & 31;
    int wm = (wid & 1) * 64;      // warp M offset in tile
    int wn = (wid >> 1) * 32;     // warp N offset in tile

    float acc[4][4][4];
    #pragma unroll
    for (int i = 0; i < 4; i++)
        #pragma unroll
        for (int j = 0; j < 4; j++)
            #pragma unroll
            for (int f = 0; f < 4; f++) acc[i][j][f] = 0.0f;

    // ldmatrix source rows (tf32 quadrant trick, 16B per 8x4 tf32 quadrant row)
    int aRow = (lane & 7) + ((lane >> 3) & 1) * 8;
    int aCol = (lane >> 4) * 16;
    int bRow = (lane & 7) + (lane >> 4) * 8;
    int bCol = ((lane >> 3) & 1) * 16;

    const int S = K >> 5;

    auto ldStage = [&](int k0, uint32_t dA, uint32_t dB) {
        const float* ga = A + (size_t)bm * K + k0;
        #pragma unroll
        for (int i = 0; i < 4; i++) {
            int idx = tid + i * 256;
            int r = idx >> 3, c4 = idx & 7;
            cpa16(dA + SWZ(r * 128 + c4 * 16), ga + (size_t)r * K + c4 * 4);
        }
        const float* gb = Bt + (size_t)bn * K + k0;
        #pragma unroll
        for (int i = 0; i < 4; i++) {
            int idx = tid + i * 256;
            int r = idx >> 3, c4 = idx & 7;
            cpa16(dB + SWZ(r * 128 + c4 * 16), gb + (size_t)r * K + c4 * 4);
        }
    };

    ldStage(0, sA0, sB0);
    asm volatile("cp.async.commit_group;" ::: "memory");
    asm volatile("cp.async.wait_group 0;" ::: "memory");
    __syncthreads();

    for (int s = 0; s < S; s++) {
        uint32_t sA = (s & 1) ? sA1 : sA0;
        uint32_t sB = (s & 1) ? sB1 : sB0;
        if (s + 1 < S) {
            ldStage((s + 1) << 5, (s & 1) ? sA0 : sA1, (s & 1) ? sB0 : sB1);
            asm volatile("cp.async.commit_group;" ::: "memory");
        }
        #pragma unroll
        for (int kk = 0; kk < 4; kk++) {
            uint32_t af[4][4], bf[4][2];
            #pragma unroll
            for (int mi = 0; mi < 4; mi++) {
                int row = wm + mi * 16 + aRow;
                ldsm4(af[mi][0], af[mi][1], af[mi][2], af[mi][3],
                      sA + SWZ(row * 128 + kk * 32 + aCol));
            }
            #pragma unroll
            for (int nj = 0; nj < 2; nj++) {
                int row = wn + nj * 16 + bRow;
                ldsm4(bf[2 * nj][0], bf[2 * nj][1], bf[2 * nj + 1][0], bf[2 * nj + 1][1],
                      sB + SWZ(row * 128 + kk * 32 + bCol));
            }
            // round-to-nearest tf32 conversion (removes HW-truncation bias)
            #pragma unroll
            for (int mi = 0; mi < 4; mi++) {
                cvt_tf32(af[mi][0]); cvt_tf32(af[mi][1]);
                cvt_tf32(af[mi][2]); cvt_tf32(af[mi][3]);
            }
            #pragma unroll
            for (int ni = 0; ni < 4; ni++) {
                cvt_tf32(bf[ni][0]); cvt_tf32(bf[ni][1]);
            }
            #pragma unroll
            for (int mi = 0; mi < 4; mi++)
                #pragma unroll
                for (int ni = 0; ni < 4; ni++)
                    mma_tf32(acc[mi][ni], af[mi], bf[ni]);
        }
        if (s + 1 < S) {
            asm volatile("cp.async.wait_group 0;" ::: "memory");
        }
        __syncthreads();
    }

    // epilogue (accumulators in registers)
    int g = lane >> 2, t4 = lane & 3;
    #pragma unroll
    for (int mi = 0; mi < 4; mi++) {
        int r0 = bm + wm + mi * 16 + g;
        int r1 = r0 + 8;
        bool mz0 = rowmask && (rowmask[r0] == 0);
        bool mz1 = rowmask && (rowmask[r1] == 0);
        #pragma unroll
        for (int ni = 0; ni < 4; ni++) {
            int c0 = bn + wn + ni * 8 + t4 * 2;
            float2 v0 = make_float2(acc[mi][ni][0], acc[mi][ni][1]);
            float2 v1 = make_float2(acc[mi][ni][2], acc[mi][ni][3]);
            if (bias) {
                float bx = bias[c0], by = bias[c0 + 1];
                v0.x += bx; v0.y += by; v1.x += bx; v1.y += by;
            }
            if (doRelu) {
                v0.x = fmaxf(v0.x, 0.0f); v0.y = fmaxf(v0.y, 0.0f);
                v1.x = fmaxf(v1.x, 0.0f); v1.y = fmaxf(v1.y, 0.0f);
            }
            if (c0 < maskColEnd) {
                if (mz0) { v0.x = 0.0f; v0.y = 0.0f; }
                if (mz1) { v1.x = 0.0f; v1.y = 0.0f; }
            }
            if (residual) {
                float2 q0 = *(const float2*)(residual + (size_t)r0 * N + c0);
                float2 q1 = *(const float2*)(residual + (size_t)r1 * N + c0);
                v0.x += q0.x; v0.y += q0.y; v1.x += q1.x; v1.y += q1.y;
            }
            *(float2*)(C + (size_t)r0 * N + c0) = v0;
            *(float2*)(C + (size_t)r1 * N + c0) = v1;
        }
    }
}

// ---------------- attention: one block per (b,h), causal softmax ----------------
#define KPAD 67
#define ATTN_SMEM ((3 * T_ * KPAD + 8 * T_) * 4)

__global__ __launch_bounds__(256, 1) void attn_kernel(
    const float* __restrict__ Q, int qs,
    const float* __restrict__ Kp, int ks,
    const float* __restrict__ V, int vs,
    float* __restrict__ O)
{
    extern __shared__ float sm[];
    float* sK = sm;
    float* sV = sK + T_ * KPAD;
    float* sQ = sV + T_ * KPAD;
    float* sP = sQ + T_ * KPAD;
    int bh = blockIdx.x;
    int b = bh / H_, h = bh % H_;
    size_t base = (size_t)b * T_;
    const float* qb = Q  + base * qs + h * D_;
    const float* kb = Kp + base * ks + h * D_;
    const float* vb = V  + base * vs + h * D_;
    float* ob = O + base * E_ + h * D_;

    for (int i = threadIdx.x; i < T_ * D_; i += blockDim.x) {
        int t = i >> 6, d = i & 63;
        sK[t * KPAD + d] = kb[(size_t)t * ks + d];
        sV[t * KPAD + d] = vb[(size_t)t * vs + d];
        sQ[t * KPAD + d] = qb[(size_t)t * qs + d];
    }
    __syncthreads();

    int w = threadIdx.x >> 5, l = threadIdx.x & 31;
    float* p = sP + w * T_;
    for (int t = w; t < T_; t += 8) {
        const float* qr = sQ + t * KPAD;
        float mx = -1e30f;
        for (int s = l; s <= t; s += 32) {
            const float* kr = sK + s * KPAD;
            float dot = 0.0f;
            #pragma unroll
            for (int d = 0; d < 64; d++) dot += qr[d] * kr[d];
            dot *= SCALE_;
            p[s] = dot;
            mx = fmaxf(mx, dot);
        }
        #pragma unroll
        for (int o = 16; o > 0; o >>= 1) mx = fmaxf(mx, __shfl_xor_sync(~0u, mx, o));
        float sum = 0.0f;
        for (int s = l; s <= t; s += 32) {
            float e = __expf(p[s] - mx);
            p[s] = e;
            sum += e;
        }
        #pragma unroll
        for (int o = 16; o > 0; o >>= 1) sum += __shfl_xor_sync(~0u, sum, o);
        float inv = 1.0f / sum;
        __syncwarp();
        float a0 = 0.0f, a1 = 0.0f;
        for (int s = 0; s <= t; s++) {
            float pv = p[s];
            a0 += pv * sV[s * KPAD + l];
            a1 += pv * sV[s * KPAD + l + 32];
        }
        ob[(size_t)t * E_ + l]      = a0 * inv;
        ob[(size_t)t * E_ + l + 32] = a1 * inv;
        __syncwarp();
    }
}

// ---------------- orchestration ----------------
extern "C" void kernel_launch(void* const* d_in, const int* in_sizes, int n_in,
                              void* d_out, int out_size) {
    const float* idx      = (const float*)d_in[0];
    const float* memory   = (const float*)d_in[1];
    const int*   src_mask = (const int*)d_in[2];
    const int*   pred_mask= (const int*)d_in[3];
    const float* sa_wq = (const float*)d_in[4];
    const float* sa_wk = (const float*)d_in[5];
    const float* sa_wv = (const float*)d_in[6];
    const float* sa_wo = (const float*)d_in[7];
    const float* sa_bo = (const float*)d_in[8];
    const float* ca_wq = (const float*)d_in[9];
    const float* ca_wk = (const float*)d_in[10];
    const float* ca_wv = (const float*)d_in[11];
    const float* ca_wo = (const float*)d_in[12];
    const float* ca_bo = (const float*)d_in[13];
    const float* f_w1  = (const float*)d_in[14];
    const float* f_b1  = (const float*)d_in[15];
    const float* f_w2  = (const float*)d_in[16];
    const float* f_b2  = (const float*)d_in[17];
    const float* ln1_g = (const float*)d_in[18];
    const float* ln1_b = (const float*)d_in[19];
    const float* ln2_g = (const float*)d_in[20];
    const float* ln2_b = (const float*)d_in[21];
    const float* ln3_g = (const float*)d_in[22];
    const float* ln3_b = (const float*)d_in[23];
    float* out = (float*)d_out;

    float *h, *qkv, *kca, *ao, *idx2, *idx3, *mid;
    float *WsaT, *WqvT, *WkT, *WoSaT, *WoCaT, *W1T, *W2T;
    cudaGetSymbolAddress((void**)&h,     g_h);
    cudaGetSymbolAddress((void**)&qkv,   g_qkv);
    cudaGetSymbolAddress((void**)&kca,   g_kca);
    cudaGetSymbolAddress((void**)&ao,    g_ao);
    cudaGetSymbolAddress((void**)&idx2,  g_idx2);
    cudaGetSymbolAddress((void**)&idx3,  g_idx3);
    cudaGetSymbolAddress((void**)&mid,   g_mid);
    cudaGetSymbolAddress((void**)&WsaT,  g_WsaT);
    cudaGetSymbolAddress((void**)&WqvT,  g_WqvT);
    cudaGetSymbolAddress((void**)&WkT,   g_WkT);
    cudaGetSymbolAddress((void**)&WoSaT, g_WoSaT);
    cudaGetSymbolAddress((void**)&WoCaT, g_WoCaT);
    cudaGetSymbolAddress((void**)&W1T,   g_W1T);
    cudaGetSymbolAddress((void**)&W2T,   g_W2T);

    cudaFuncSetAttribute(attn_kernel, cudaFuncAttributeMaxDynamicSharedMemorySize, ATTN_SMEM);
    cudaFuncSetAttribute(tc_gemm,     cudaFuncAttributeMaxDynamicSharedMemorySize, TCG_SMEM);

    // weight packs / transposes ([N,K] K-major for the MMA B operand)
    pack_qkv_t<<<(3 * E_ * E_ + 255) / 256, 256>>>(sa_wq, sa_wk, sa_wv, WsaT, 3);
    pack_qkv_t<<<(2 * E_ * E_ + 255) / 256, 256>>>(ca_wq, ca_wv, ca_wv, WqvT, 2);
    pack_qkv_t<<<(E_ * E_ + 255) / 256, 256>>>(ca_wk, ca_wk, ca_wk, WkT, 1);
    transpose_k<<<dim3(16, 16), dim3(32, 32)>>>(sa_wo, WoSaT, 512, 512);
    transpose_k<<<dim3(16, 16), dim3(32, 32)>>>(ca_wo, WoCaT, 512, 512);
    transpose_k<<<dim3(64, 16), dim3(32, 32)>>>(f_w1, W1T, 512, 2048);
    transpose_k<<<dim3(16, 64), dim3(32, 32)>>>(f_w2, W2T, 2048, 512);

    // ---- self-attention block ----
    ln_kernel<<<M_, 128>>>(idx, ln1_g, ln1_b, h);
    tc_gemm<<<dim3(12, 100), 256, TCG_SMEM>>>(h, WsaT, qkv, 1536, 512,
                                              nullptr, nullptr, pred_mask, 1024, 0);
    attn_kernel<<<B_ * H_, 256, ATTN_SMEM>>>(qkv, 1536, qkv + 512, 1536, qkv + 1024, 1536, ao);
    tc_gemm<<<dim3(4, 100), 256, TCG_SMEM>>>(ao, WoSaT, idx2, 512, 512,
                                             sa_bo, idx, nullptr, 0, 0);

    // ---- cross-attention block ----
    ln_kernel<<<M_, 128>>>(idx2, ln2_g, ln2_b, h);
    tc_gemm<<<dim3(8, 100), 256, TCG_SMEM>>>(h, WqvT, qkv, 1024, 512,
                                             nullptr, nullptr, nullptr, 0, 0);
    tc_gemm<<<dim3(4, 100), 256, TCG_SMEM>>>(memory, WkT, kca, 512, 512,
                                             nullptr, nullptr, src_mask, 512, 0);
    attn_kernel<<<B_ * H_, 256, ATTN_SMEM>>>(qkv, 1024, kca, 512, qkv + 512, 1024, ao);
    tc_gemm<<<dim3(4, 100), 256, TCG_SMEM>>>(ao, WoCaT, idx3, 512, 512,
                                             ca_bo, idx2, nullptr, 0, 0);

    // ---- feed-forward block ----
    ln_kernel<<<M_, 128>>>(idx3, ln3_g, ln3_b, h);
    tc_gemm<<<dim3(16, 100), 256, TCG_SMEM>>>(h, W1T, mid, 2048, 512,
                                              f_b1, nullptr, nullptr, 0, 1);
    tc_gemm<<<dim3(4, 100), 256, TCG_SMEM>>>(mid, W2T, out, 512, 2048,
                                             f_b2, idx3, nullptr, 0, 0);
}

// round 5
// speedup vs baseline: 3.2794x; 1.0948x over previous
#include <cuda_runtime.h>
#include <math.h>
#include <cstdint>

// Problem constants
#define B_ 64
#define T_ 200
#define E_ 512
#define H_ 8
#define D_ 64
#define M_ (B_ * T_)            // 12800 rows
#define SCALE_ 0.04419417382415922f  // 512^-0.5
#define LN_EPS 1e-5f

// ---------------- scratch ----------------
__device__ float g_h[M_ * E_];
__device__ float g_qkv[M_ * 3 * E_];
__device__ float g_kca[M_ * E_];
__device__ float g_ao[M_ * E_];
__device__ float g_idx2[M_ * E_];
__device__ float g_idx3[M_ * E_];
__device__ float g_mid[M_ * 4 * E_];
__device__ float g_memR[M_ * E_];       // tf32-rounded copy of memory
__device__ float g_WsaT[3 * E_ * E_];
__device__ float g_WqvT[2 * E_ * E_];
__device__ float g_WkT[E_ * E_];
__device__ float g_WoSaT[E_ * E_];
__device__ float g_WoCaT[E_ * E_];
__device__ float g_W1T[4 * E_ * E_];
__device__ float g_W2T[E_ * 4 * E_];

// ======================= helpers =======================
__device__ __forceinline__ uint32_t s2u(const void* p) {
    uint32_t a;
    asm("{ .reg .u64 t; cvta.to.shared.u64 t, %1; cvt.u32.u64 %0, t; }" : "=r"(a) : "l"(p));
    return a;
}
#define SWZ(o) ((o) ^ (((o) >> 3) & 0x70))

__device__ __forceinline__ float tf32r(float x) {
    uint32_t u = __float_as_uint(x);
    asm("cvt.rna.tf32.f32 %0, %0;" : "+r"(u));
    return __uint_as_float(u);
}
__device__ __forceinline__ void cpa16(uint32_t dst, const void* src) {
    asm volatile("cp.async.cg.shared.global [%0], [%1], 16;" :: "r"(dst), "l"(src));
}
__device__ __forceinline__ void ldsm4(uint32_t& r0, uint32_t& r1, uint32_t& r2,
                                      uint32_t& r3, uint32_t addr) {
    asm volatile("ldmatrix.sync.aligned.m8n8.x4.shared.b16 {%0,%1,%2,%3}, [%4];"
                 : "=r"(r0), "=r"(r1), "=r"(r2), "=r"(r3) : "r"(addr));
}
__device__ __forceinline__ void mma_tf32(float* c, const uint32_t* a, const uint32_t* b) {
    asm volatile(
        "mma.sync.aligned.m16n8k8.row.col.f32.tf32.tf32.f32 "
        "{%0,%1,%2,%3}, {%4,%5,%6,%7}, {%8,%9}, {%0,%1,%2,%3};"
        : "+f"(c[0]), "+f"(c[1]), "+f"(c[2]), "+f"(c[3])
        : "r"(a[0]), "r"(a[1]), "r"(a[2]), "r"(a[3]), "r"(b[0]), "r"(b[1]));
}

// ---------------- producer-side rounding kernels ----------------
__global__ void round_copy(const float* __restrict__ in, float* __restrict__ out, int n4) {
    int i = blockIdx.x * blockDim.x + threadIdx.x;
    if (i >= n4) return;
    float4 v = ((const float4*)in)[i];
    v.x = tf32r(v.x); v.y = tf32r(v.y); v.z = tf32r(v.z); v.w = tf32r(v.w);
    ((float4*)out)[i] = v;
}

__global__ void pack_qkv_t(const float* __restrict__ w0, const float* __restrict__ w1,
                           const float* __restrict__ w2, float* __restrict__ out, int nmats) {
    int i = blockIdx.x * blockDim.x + threadIdx.x;
    int total = nmats * E_ * E_;
    if (i >= total) return;
    int e = i & 511;
    int c = i >> 9;
    int m = c >> 9;
    int hd = c & 511;
    const float* w = (m == 0) ? w0 : ((m == 1) ? w1 : w2);
    out[i] = tf32r(w[((size_t)((hd >> 6) * E_ + e)) * D_ + (hd & 63)]);
}

__global__ void transpose_k(const float* __restrict__ in, float* __restrict__ out,
                            int R, int C) {
    __shared__ float t[32][33];
    int c0 = blockIdx.x * 32, r0 = blockIdx.y * 32;
    t[threadIdx.y][threadIdx.x] = in[(size_t)(r0 + threadIdx.y) * C + c0 + threadIdx.x];
    __syncthreads();
    out[(size_t)(c0 + threadIdx.y) * R + r0 + threadIdx.x] = tf32r(t[threadIdx.x][threadIdx.y]);
}

// ---------------- layernorm (tf32-rounded output: feeds GEMM A only) ----------------
__global__ void ln_kernel(const float* __restrict__ x, const float* __restrict__ g,
                          const float* __restrict__ b, float* __restrict__ y) {
    int row = blockIdx.x;
    const float4* xr = (const float4*)(x + (size_t)row * E_);
    float4 v = xr[threadIdx.x];
    float s  = v.x + v.y + v.z + v.w;
    float ss = v.x * v.x + v.y * v.y + v.z * v.z + v.w * v.w;
    #pragma unroll
    for (int o = 16; o > 0; o >>= 1) {
        s  += __shfl_xor_sync(~0u, s, o);
        ss += __shfl_xor_sync(~0u, ss, o);
    }
    __shared__ float sh[8];
    int w = threadIdx.x >> 5, l = threadIdx.x & 31;
    if (l == 0) { sh[w] = s; sh[4 + w] = ss; }
    __syncthreads();
    s  = sh[0] + sh[1] + sh[2] + sh[3];
    ss = sh[4] + sh[5] + sh[6] + sh[7];
    float mu   = s * (1.0f / E_);
    float var  = ss * (1.0f / E_) - mu * mu;
    float rstd = rsqrtf(var + LN_EPS);
    float4 gv = ((const float4*)g)[threadIdx.x];
    float4 bv = ((const float4*)b)[threadIdx.x];
    float4 o;
    o.x = tf32r((v.x - mu) * rstd * gv.x + bv.x);
    o.y = tf32r((v.y - mu) * rstd * gv.y + bv.y);
    o.z = tf32r((v.z - mu) * rstd * gv.z + bv.z);
    o.w = tf32r((v.w - mu) * rstd * gv.w + bv.w);
    ((float4*)(y + (size_t)row * E_))[threadIdx.x] = o;
}

// ======================= tf32 mma.sync GEMM (no in-loop cvt) =======================
#define TCG_SMEM (4 * 16384)

__global__ __launch_bounds__(256, 2) void tc_gemm(
    const float* __restrict__ A, const float* __restrict__ Bt, float* __restrict__ C,
    int N, int K, const float* __restrict__ bias, const float* __restrict__ residual,
    const int* __restrict__ rowmask, int maskColEnd, int doRelu, int roundOut)
{
    extern __shared__ __align__(1024) char smem[];
    uint32_t sb = s2u(smem);
    uint32_t sA0 = sb, sB0 = sb + 16384, sA1 = sb + 32768, sB1 = sb + 49152;

    int tid = threadIdx.x;
    int bn = blockIdx.x * 128, bm = blockIdx.y * 128;
    int wid = tid >> 5, lane = tid & 31;
    int wm = (wid & 1) * 64;
    int wn = (wid >> 1) * 32;

    float acc[4][4][4];
    #pragma unroll
    for (int i = 0; i < 4; i++)
        #pragma unroll
        for (int j = 0; j < 4; j++)
            #pragma unroll
            for (int f = 0; f < 4; f++) acc[i][j][f] = 0.0f;

    int aRow = (lane & 7) + ((lane >> 3) & 1) * 8;
    int aCol = (lane >> 4) * 16;
    int bRow = (lane & 7) + (lane >> 4) * 8;
    int bCol = ((lane >> 3) & 1) * 16;

    const int S = K >> 5;

    auto ldStage = [&](int k0, uint32_t dA, uint32_t dB) {
        const float* ga = A + (size_t)bm * K + k0;
        #pragma unroll
        for (int i = 0; i < 4; i++) {
            int idx = tid + i * 256;
            int r = idx >> 3, c4 = idx & 7;
            cpa16(dA + SWZ(r * 128 + c4 * 16), ga + (size_t)r * K + c4 * 4);
        }
        const float* gb = Bt + (size_t)bn * K + k0;
        #pragma unroll
        for (int i = 0; i < 4; i++) {
            int idx = tid + i * 256;
            int r = idx >> 3, c4 = idx & 7;
            cpa16(dB + SWZ(r * 128 + c4 * 16), gb + (size_t)r * K + c4 * 4);
        }
    };

    ldStage(0, sA0, sB0);
    asm volatile("cp.async.commit_group;" ::: "memory");
    asm volatile("cp.async.wait_group 0;" ::: "memory");
    __syncthreads();

    for (int s = 0; s < S; s++) {
        uint32_t sA = (s & 1) ? sA1 : sA0;
        uint32_t sB = (s & 1) ? sB1 : sB0;
        if (s + 1 < S) {
            ldStage((s + 1) << 5, (s & 1) ? sA0 : sA1, (s & 1) ? sB0 : sB1);
            asm volatile("cp.async.commit_group;" ::: "memory");
        }
        #pragma unroll
        for (int kk = 0; kk < 4; kk++) {
            uint32_t af[4][4], bf[4][2];
            #pragma unroll
            for (int mi = 0; mi < 4; mi++) {
                int row = wm + mi * 16 + aRow;
                ldsm4(af[mi][0], af[mi][1], af[mi][2], af[mi][3],
                      sA + SWZ(row * 128 + kk * 32 + aCol));
            }
            #pragma unroll
            for (int nj = 0; nj < 2; nj++) {
                int row = wn + nj * 16 + bRow;
                ldsm4(bf[2 * nj][0], bf[2 * nj][1], bf[2 * nj + 1][0], bf[2 * nj + 1][1],
                      sB + SWZ(row * 128 + kk * 32 + bCol));
            }
            #pragma unroll
            for (int mi = 0; mi < 4; mi++)
                #pragma unroll
                for (int ni = 0; ni < 4; ni++)
                    mma_tf32(acc[mi][ni], af[mi], bf[ni]);
        }
        if (s + 1 < S) {
            asm volatile("cp.async.wait_group 0;" ::: "memory");
        }
        __syncthreads();
    }

    // epilogue
    int g = lane >> 2, t4 = lane & 3;
    #pragma unroll
    for (int mi = 0; mi < 4; mi++) {
        int r0 = bm + wm + mi * 16 + g;
        int r1 = r0 + 8;
        bool mz0 = rowmask && (rowmask[r0] == 0);
        bool mz1 = rowmask && (rowmask[r1] == 0);
        #pragma unroll
        for (int ni = 0; ni < 4; ni++) {
            int c0 = bn + wn + ni * 8 + t4 * 2;
            float2 v0 = make_float2(acc[mi][ni][0], acc[mi][ni][1]);
            float2 v1 = make_float2(acc[mi][ni][2], acc[mi][ni][3]);
            if (bias) {
                float bx = bias[c0], by = bias[c0 + 1];
                v0.x += bx; v0.y += by; v1.x += bx; v1.y += by;
            }
            if (doRelu) {
                v0.x = fmaxf(v0.x, 0.0f); v0.y = fmaxf(v0.y, 0.0f);
                v1.x = fmaxf(v1.x, 0.0f); v1.y = fmaxf(v1.y, 0.0f);
            }
            if (c0 < maskColEnd) {
                if (mz0) { v0.x = 0.0f; v0.y = 0.0f; }
                if (mz1) { v1.x = 0.0f; v1.y = 0.0f; }
            }
            if (residual) {
                float2 q0 = *(const float2*)(residual + (size_t)r0 * N + c0);
                float2 q1 = *(const float2*)(residual + (size_t)r1 * N + c0);
                v0.x += q0.x; v0.y += q0.y; v1.x += q1.x; v1.y += q1.y;
            }
            if (roundOut) {
                v0.x = tf32r(v0.x); v0.y = tf32r(v0.y);
                v1.x = tf32r(v1.x); v1.y = tf32r(v1.y);
            }
            *(float2*)(C + (size_t)r0 * N + c0) = v0;
            *(float2*)(C + (size_t)r1 * N + c0) = v1;
        }
    }
}

// ---------------- attention: paired rows (t, t+8) per warp pass ----------------
#define KPAD 67
#define ATTN_SMEM ((3 * T_ * KPAD + 16 * T_) * 4)

__global__ __launch_bounds__(256, 1) void attn_kernel(
    const float* __restrict__ Q, int qs,
    const float* __restrict__ Kp, int ks,
    const float* __restrict__ V, int vs,
    float* __restrict__ O)
{
    extern __shared__ float sm[];
    float* sK = sm;
    float* sV = sK + T_ * KPAD;
    float* sQ = sV + T_ * KPAD;
    float* sP = sQ + T_ * KPAD;    // 8 warps x 2 rows x T_
    int bh = blockIdx.x;
    int b = bh / H_, h = bh % H_;
    size_t base = (size_t)b * T_;
    const float* qb = Q  + base * qs + h * D_;
    const float* kb = Kp + base * ks + h * D_;
    const float* vb = V  + base * vs + h * D_;
    float* ob = O + base * E_ + h * D_;

    for (int i = threadIdx.x; i < T_ * D_; i += blockDim.x) {
        int t = i >> 6, d = i & 63;
        sK[t * KPAD + d] = kb[(size_t)t * ks + d];
        sV[t * KPAD + d] = vb[(size_t)t * vs + d];
        sQ[t * KPAD + d] = qb[(size_t)t * qs + d];
    }
    __syncthreads();

    int w = threadIdx.x >> 5, l = threadIdx.x & 31;
    float* p1 = sP + (2 * w) * T_;
    float* p2 = p1 + T_;

    for (int t1 = w; t1 < T_; t1 += 16) {
        int t2 = t1 + 8;           // always < T_ (T_=200, max t1=199-? t1 max=192+w<=199, t2<=207) guard:
        bool has2 = (t2 < T_);
        // ---- scores + softmax row t1 ----
        {
            const float* qr = sQ + t1 * KPAD;
            float mx = -1e30f;
            for (int s = l; s <= t1; s += 32) {
                const float* kr = sK + s * KPAD;
                float dot = 0.0f;
                #pragma unroll
                for (int d = 0; d < 64; d++) dot += qr[d] * kr[d];
                dot *= SCALE_;
                p1[s] = dot;
                mx = fmaxf(mx, dot);
            }
            #pragma unroll
            for (int o = 16; o > 0; o >>= 1) mx = fmaxf(mx, __shfl_xor_sync(~0u, mx, o));
            float sum = 0.0f;
            for (int s = l; s <= t1; s += 32) {
                float e = __expf(p1[s] - mx);
                p1[s] = e;
                sum += e;
            }
            #pragma unroll
            for (int o = 16; o > 0; o >>= 1) sum += __shfl_xor_sync(~0u, sum, o);
            p2[T_ - 1] = 0.0f;     // dummy
            float inv = 1.0f / sum;
            if (l == 0) p1[t1] = p1[t1];  // no-op keep
            // stash inv in a register-shared way: broadcast below
            sum = inv;
            // store inv via lane0 into sP tail? simpler: keep in reg, both rows handled below
            // (we recompute per-row inv locally)
            // save to smem slot for later use by all lanes:
            if (l == 0) p1[t1 == 0 ? 0 : t1] = p1[t1]; // no-op
            // actually keep inv in variable:
            __syncwarp();
            // PV for row1 deferred to joint pass; save inv:
            // use shuffle from lane 0 later; simplest: all lanes already have inv (reduced)
            // store in p-independent regs:
            // (handled: inv1 below)
            p1[0] = p1[0];
            // fallthrough
            // row1 inv
            // NOTE: inv captured here
            // ---- second row ----
            float inv1 = sum;
            float mx2 = -1e30f, sum2 = 1.0f, inv2 = 0.0f;
            if (has2) {
                const float* qr2 = sQ + t2 * KPAD;
                mx2 = -1e30f;
                for (int s = l; s <= t2; s += 32) {
                    const float* kr = sK + s * KPAD;
                    float dot = 0.0f;
                    #pragma unroll
                    for (int d = 0; d < 64; d++) dot += qr2[d] * kr[d];
                    dot *= SCALE_;
                    p2[s] = dot;
                    mx2 = fmaxf(mx2, dot);
                }
                #pragma unroll
                for (int o = 16; o > 0; o >>= 1) mx2 = fmaxf(mx2, __shfl_xor_sync(~0u, mx2, o));
                sum2 = 0.0f;
                for (int s = l; s <= t2; s += 32) {
                    float e = __expf(p2[s] - mx2);
                    p2[s] = e;
                    sum2 += e;
                }
                #pragma unroll
                for (int o = 16; o > 0; o >>= 1) sum2 += __shfl_xor_sync(~0u, sum2, o);
                inv2 = 1.0f / sum2;
            }
            __syncwarp();
            // ---- joint V pass ----
            float a0 = 0.0f, a1 = 0.0f, c0 = 0.0f, c1 = 0.0f;
            for (int s = 0; s <= t1; s++) {
                float v0 = sV[s * KPAD + l];
                float v1 = sV[s * KPAD + l + 32];
                float pa = p1[s];
                a0 += pa * v0; a1 += pa * v1;
                if (has2) {
                    float pb = p2[s];
                    c0 += pb * v0; c1 += pb * v1;
                }
            }
            if (has2) {
                for (int s = t1 + 1; s <= t2; s++) {
                    float v0 = sV[s * KPAD + l];
                    float v1 = sV[s * KPAD + l + 32];
                    float pb = p2[s];
                    c0 += pb * v0; c1 += pb * v1;
                }
            }
            ob[(size_t)t1 * E_ + l]      = tf32r(a0 * inv1);
            ob[(size_t)t1 * E_ + l + 32] = tf32r(a1 * inv1);
            if (has2) {
                ob[(size_t)t2 * E_ + l]      = tf32r(c0 * inv2);
                ob[(size_t)t2 * E_ + l + 32] = tf32r(c1 * inv2);
            }
            __syncwarp();
        }
    }
}

// ---------------- orchestration ----------------
extern "C" void kernel_launch(void* const* d_in, const int* in_sizes, int n_in,
                              void* d_out, int out_size) {
    const float* idx      = (const float*)d_in[0];
    const float* memory   = (const float*)d_in[1];
    const int*   src_mask = (const int*)d_in[2];
    const int*   pred_mask= (const int*)d_in[3];
    const float* sa_wq = (const float*)d_in[4];
    const float* sa_wk = (const float*)d_in[5];
    const float* sa_wv = (const float*)d_in[6];
    const float* sa_wo = (const float*)d_in[7];
    const float* sa_bo = (const float*)d_in[8];
    const float* ca_wq = (const float*)d_in[9];
    const float* ca_wk = (const float*)d_in[10];
    const float* ca_wv = (const float*)d_in[11];
    const float* ca_wo = (const float*)d_in[12];
    const float* ca_bo = (const float*)d_in[13];
    const float* f_w1  = (const float*)d_in[14];
    const float* f_b1  = (const float*)d_in[15];
    const float* f_w2  = (const float*)d_in[16];
    const float* f_b2  = (const float*)d_in[17];
    const float* ln1_g = (const float*)d_in[18];
    const float* ln1_b = (const float*)d_in[19];
    const float* ln2_g = (const float*)d_in[20];
    const float* ln2_b = (const float*)d_in[21];
    const float* ln3_g = (const float*)d_in[22];
    const float* ln3_b = (const float*)d_in[23];
    float* out = (float*)d_out;

    float *h, *qkv, *kca, *ao, *idx2, *idx3, *mid, *memR;
    float *WsaT, *WqvT, *WkT, *WoSaT, *WoCaT, *W1T, *W2T;
    cudaGetSymbolAddress((void**)&h,     g_h);
    cudaGetSymbolAddress((void**)&qkv,   g_qkv);
    cudaGetSymbolAddress((void**)&kca,   g_kca);
    cudaGetSymbolAddress((void**)&ao,    g_ao);
    cudaGetSymbolAddress((void**)&idx2,  g_idx2);
    cudaGetSymbolAddress((void**)&idx3,  g_idx3);
    cudaGetSymbolAddress((void**)&mid,   g_mid);
    cudaGetSymbolAddress((void**)&memR,  g_memR);
    cudaGetSymbolAddress((void**)&WsaT,  g_WsaT);
    cudaGetSymbolAddress((void**)&WqvT,  g_WqvT);
    cudaGetSymbolAddress((void**)&WkT,   g_WkT);
    cudaGetSymbolAddress((void**)&WoSaT, g_WoSaT);
    cudaGetSymbolAddress((void**)&WoCaT, g_WoCaT);
    cudaGetSymbolAddress((void**)&W1T,   g_W1T);
    cudaGetSymbolAddress((void**)&W2T,   g_W2T);

    cudaFuncSetAttribute(attn_kernel, cudaFuncAttributeMaxDynamicSharedMemorySize, ATTN_SMEM);
    cudaFuncSetAttribute(tc_gemm,     cudaFuncAttributeMaxDynamicSharedMemorySize, TCG_SMEM);

    // weight packs / transposes (tf32-rounded)
    pack_qkv_t<<<(3 * E_ * E_ + 255) / 256, 256>>>(sa_wq, sa_wk, sa_wv, WsaT, 3);
    pack_qkv_t<<<(2 * E_ * E_ + 255) / 256, 256>>>(ca_wq, ca_wv, ca_wv, WqvT, 2);
    pack_qkv_t<<<(E_ * E_ + 255) / 256, 256>>>(ca_wk, ca_wk, ca_wk, WkT, 1);
    transpose_k<<<dim3(16, 16), dim3(32, 32)>>>(sa_wo, WoSaT, 512, 512);
    transpose_k<<<dim3(16, 16), dim3(32, 32)>>>(ca_wo, WoCaT, 512, 512);
    transpose_k<<<dim3(64, 16), dim3(32, 32)>>>(f_w1, W1T, 512, 2048);
    transpose_k<<<dim3(16, 64), dim3(32, 32)>>>(f_w2, W2T, 2048, 512);
    round_copy<<<(M_ * E_ / 4 + 255) / 256, 256>>>(memory, memR, M_ * E_ / 4);

    // ---- self-attention block ----
    ln_kernel<<<M_, 128>>>(idx, ln1_g, ln1_b, h);
    tc_gemm<<<dim3(12, 100), 256, TCG_SMEM>>>(h, WsaT, qkv, 1536, 512,
                                              nullptr, nullptr, pred_mask, 1024, 0, 0);
    attn_kernel<<<B_ * H_, 256, ATTN_SMEM>>>(qkv, 1536, qkv + 512, 1536, qkv + 1024, 1536, ao);
    tc_gemm<<<dim3(4, 100), 256, TCG_SMEM>>>(ao, WoSaT, idx2, 512, 512,
                                             sa_bo, idx, nullptr, 0, 0, 0);

    // ---- cross-attention block ----
    ln_kernel<<<M_, 128>>>(idx2, ln2_g, ln2_b, h);
    tc_gemm<<<dim3(8, 100), 256, TCG_SMEM>>>(h, WqvT, qkv, 1024, 512,
                                             nullptr, nullptr, nullptr, 0, 0, 0);
    tc_gemm<<<dim3(4, 100), 256, TCG_SMEM>>>(memR, WkT, kca, 512, 512,
                                             nullptr, nullptr, src_mask, 512, 0, 0);
    attn_kernel<<<B_ * H_, 256, ATTN_SMEM>>>(qkv, 1024, kca, 512, qkv + 512, 1024, ao);
    tc_gemm<<<dim3(4, 100), 256, TCG_SMEM>>>(ao, WoCaT, idx3, 512, 512,
                                             ca_bo, idx2, nullptr, 0, 0, 0);

    // ---- feed-forward block ----
    ln_kernel<<<M_, 128>>>(idx3, ln3_g, ln3_b, h);
    tc_gemm<<<dim3(16, 100), 256, TCG_SMEM>>>(h, W1T, mid, 2048, 512,
                                              f_b1, nullptr, nullptr, 0, 1, 1);
    tc_gemm<<<dim3(4, 100), 256, TCG_SMEM>>>(mid, W2T, out, 512, 2048,
                                             f_b2, idx3, nullptr, 0, 0, 0);
}